// round 13
// baseline (speedup 1.0000x reference)
#include <cuda_runtime.h>
#include <cuda_bf16.h>
#include <math.h>
#include <stdint.h>
#include <mma.h>

using namespace nvcuda;
typedef __nv_bfloat16 bf16;

#define B_ 1024
#define T_ 16
#define D_ 1024
#define H_ 2048
#define O_ 1024

// ==================== device globals ========================================
__device__ int   r13_flag, r13_viol;
__device__ float r13_inp[B_ * T_ * H_];
__device__ float r13_preall[B_ * T_ * H_];
__device__ float r13_pre[B_ * H_];
__device__ float r13_sf[B_ * H_];
__device__ float r13_gf[B_ * H_];
__device__ float r13_ctx[B_ * H_], r13_rec[B_ * H_];
__device__ float r13_attrA[B_ * H_], r13_attrB[B_ * H_];
__device__ float r13_spk[B_ * H_];
__device__ float r13_testF[128 * H_], r13_testT[128 * H_];

__device__ bf16 r13_xb0[B_ * T_ * D_], r13_xb1[B_ * T_ * D_], r13_xb2[B_ * T_ * D_];
__device__ bf16 r13_ib0[B_ * T_ * H_], r13_ib1[B_ * T_ * H_], r13_ib2[B_ * T_ * H_];
__device__ bf16 r13_Wp0[H_ * D_], r13_Wp1[H_ * D_], r13_Wp2[H_ * D_];
__device__ bf16 r13_Wfc0[H_ * H_], r13_Wfc1[H_ * H_], r13_Wfc2[H_ * H_];
__device__ bf16 r13_Wg0[H_ * H_], r13_Wg1[H_ * H_], r13_Wg2[H_ * H_];
__device__ bf16 r13_We0[H_ * H_], r13_We1[H_ * H_], r13_We2[H_ * H_];
__device__ bf16 r13_Wr0[H_ * H_], r13_Wr1[H_ * H_], r13_Wr2[H_ * H_];
__device__ bf16 r13_Wo0[O_ * H_], r13_Wo1[O_ * H_], r13_Wo2[O_ * H_];
__device__ bf16 r13_sb0[B_ * H_], r13_sb1[B_ * H_], r13_sb2[B_ * H_];
__device__ bf16 r13_gb0[B_ * H_], r13_gb1[B_ * H_], r13_gb2[B_ * H_];
__device__ bf16 r13_ab0[B_ * H_], r13_ab1[B_ * H_], r13_ab2[B_ * H_];
__device__ bf16 r13_pb0[B_ * H_], r13_pb1[B_ * H_], r13_pb2[B_ * H_];

// ==================== helpers ===============================================
__device__ __forceinline__ void r13_split3(float v, bf16* s) {
    s[0] = __float2bfloat16(v);
    float r = v - __bfloat162float(s[0]);
    s[1] = __float2bfloat16(r);
    r -= __bfloat162float(s[1]);
    s[2] = __float2bfloat16(r);
}
__device__ __forceinline__ uint32_t r13_smem_u32(const void* p) {
    uint32_t a;
    asm("{ .reg .u64 t; cvta.to.shared.u64 t, %1; cvt.u32.u64 %0, t; }" : "=r"(a) : "l"(p));
    return a;
}
__device__ __forceinline__ void r13_cp16(uint32_t dst, const void* src) {
    asm volatile("cp.async.cg.shared.global [%0], [%1], 16;" :: "r"(dst), "l"(src));
}

// ==================== fp32 SGEMM (proven engine, gated on flag==0) ==========
__global__ void __launch_bounds__(256) r13_sgemm(
    const int* gate,
    const float* __restrict__ A1, int lda1, const float* __restrict__ B1,
    const float* __restrict__ A2, int lda2, const float* __restrict__ B2,
    const float* __restrict__ bias1, const float* __restrict__ bias2,
    float* __restrict__ C, int ldc, int M, int N, int K, float alpha)
{
    if (gate && (*(volatile const int*)gate) != 0) return;
    const int BM = 128, BN = 128, BK = 16;
    __shared__ float As[BK][BM];
    __shared__ float Bs[BK][BN];
    const int bm = blockIdx.y * BM, bn = blockIdx.x * BN;
    const int tid = threadIdx.x, tr = tid / 16, tc = tid % 16;
    const int a_r = tid / 4, a_c = (tid % 4) * 4;
    const int b_r = tid / 32, b_c = (tid % 32) * 4;

    float acc[8][8];
#pragma unroll
    for (int i = 0; i < 8; i++)
#pragma unroll
        for (int j = 0; j < 8; j++) acc[i][j] = 0.0f;

    const int npass = (A2 != nullptr) ? 2 : 1;
    for (int pass = 0; pass < npass; pass++) {
        const float* A  = pass ? A2 : A1;
        const float* Bm = pass ? B2 : B1;
        const int lda   = pass ? lda2 : lda1;
        for (int k0 = 0; k0 < K; k0 += BK) {
#pragma unroll
            for (int i = 0; i < 2; i++) {
                int r = a_r + i * 64;
                float4 v = *(const float4*)(A + (long)(bm + r) * lda + k0 + a_c);
                As[a_c + 0][r] = v.x; As[a_c + 1][r] = v.y;
                As[a_c + 2][r] = v.z; As[a_c + 3][r] = v.w;
            }
#pragma unroll
            for (int i = 0; i < 2; i++) {
                int r = b_r + i * 8;
                float4 v = *(const float4*)(Bm + (long)(k0 + r) * N + bn + b_c);
                *(float4*)&Bs[r][b_c] = v;
            }
            __syncthreads();
#pragma unroll
            for (int kk = 0; kk < BK; kk++) {
                float4 a0 = *(const float4*)&As[kk][tr * 8];
                float4 a1 = *(const float4*)&As[kk][tr * 8 + 4];
                float4 b0 = *(const float4*)&Bs[kk][tc * 8];
                float4 b1 = *(const float4*)&Bs[kk][tc * 8 + 4];
                float a[8] = {a0.x, a0.y, a0.z, a0.w, a1.x, a1.y, a1.z, a1.w};
                float b[8] = {b0.x, b0.y, b0.z, b0.w, b1.x, b1.y, b1.z, b1.w};
#pragma unroll
                for (int i = 0; i < 8; i++)
#pragma unroll
                    for (int j = 0; j < 8; j++)
                        acc[i][j] = fmaf(a[i], b[j], acc[i][j]);
            }
            __syncthreads();
        }
    }
    const int row0 = bm + tr * 8, col0 = bn + tc * 8;
    float bias[8];
#pragma unroll
    for (int j = 0; j < 8; j++) {
        float v = bias1 ? bias1[col0 + j] : 0.0f;
        if (bias2) v += bias2[col0 + j];
        bias[j] = v;
    }
#pragma unroll
    for (int i = 0; i < 8; i++) {
        float4 o0, o1;
        o0.x = alpha * acc[i][0] + bias[0]; o0.y = alpha * acc[i][1] + bias[1];
        o0.z = alpha * acc[i][2] + bias[2]; o0.w = alpha * acc[i][3] + bias[3];
        o1.x = alpha * acc[i][4] + bias[4]; o1.y = alpha * acc[i][5] + bias[5];
        o1.z = alpha * acc[i][6] + bias[6]; o1.w = alpha * acc[i][7] + bias[7];
        *(float4*)(C + (long)(row0 + i) * ldc + col0)     = o0;
        *(float4*)(C + (long)(row0 + i) * ldc + col0 + 4) = o1;
    }
}

// ==================== bf16 3-limb / 6-term tensor GEMM ======================
// CTA 128x128, 8 warps, warp tile 64x32. Two accumulator classes.
// Inner loop: i-pairs, term-major mma ordering (same-acc reuse distance = 4).
#define TBM 128
#define TBN 128
#define TBK 32
#define TLD 40
#define TARR (TBM * TLD)
#define TSTAGE (6 * TARR)
#define TSMEM (2 * TSTAGE * 2)           // 122880 bytes

struct R13P {
    const bf16 *A0, *A1, *A2;
    long lda;
    const bf16 *B0, *B1, *B2;
    int K;
};

__device__ __forceinline__ void r13_tload(
    uint32_t sb, int s, const R13P& p, int k0, int bm, int bn, int tid)
{
    const uint32_t st = sb + (uint32_t)(s * TSTAGE) * 2u;
    const bf16* arr[6] = { p.A0, p.A1, p.A2, p.B0, p.B1, p.B2 };
#pragma unroll
    for (int a = 0; a < 6; a++) {
        const long ldg = (a < 3) ? p.lda : (long)p.K;
        const int rb = (a < 3) ? bm : bn;
        const uint32_t base = st + (uint32_t)(a * TARR) * 2u;
#pragma unroll
        for (int it = 0; it < 2; it++) {
            int li = tid + it * 256;
            int row = li >> 2, c8 = (li & 3) * 8;
            r13_cp16(base + (uint32_t)(row * TLD + c8) * 2u,
                     arr[a] + (long)(rb + row) * ldg + k0 + c8);
        }
    }
    asm volatile("cp.async.commit_group;" ::: "memory");
}

__global__ void __launch_bounds__(256, 1) r13_tgemm(
    R13P p0, R13P p1, int npass, const int* gate,
    const float* __restrict__ bias1, const float* __restrict__ bias2,
    float* __restrict__ C, int ldc, float alpha)
{
    if (gate && (*(volatile const int*)gate) != 1) return;
    extern __shared__ __align__(16) bf16 sm[];
    const uint32_t sb = r13_smem_u32(sm);
    const int tid = threadIdx.x, wid = tid >> 5;
    const int bm = blockIdx.y * TBM, bn = blockIdx.x * TBN;
    const int wm = (wid & 1) * 64;
    const int wn = (wid >> 1) * 32;

    wmma::fragment<wmma::accumulator, 16, 16, 16, float> ac0[4][2], ac1[4][2];
#pragma unroll
    for (int i = 0; i < 4; i++)
#pragma unroll
        for (int j = 0; j < 2; j++) {
            wmma::fill_fragment(ac0[i][j], 0.0f);
            wmma::fill_fragment(ac1[i][j], 0.0f);
        }

    const int t0 = p0.K / TBK;
    const int t1 = (npass > 1) ? (p1.K / TBK) : 0;
    const int total = t0 + t1;

    r13_tload(sb, 0, p0, 0, bm, bn, tid);

    for (int gt = 0; gt < total; gt++) {
        const int s = gt & 1;
        if (gt + 1 < total) {
            const int nt = gt + 1;
            const bool in1 = (nt >= t0);
            r13_tload(sb, s ^ 1, in1 ? p1 : p0, (in1 ? (nt - t0) : nt) * TBK,
                      bm, bn, tid);
            asm volatile("cp.async.wait_group 1;" ::: "memory");
        } else {
            asm volatile("cp.async.wait_group 0;" ::: "memory");
        }
        __syncthreads();

        const bf16* As0 = sm + s * TSTAGE;
        const bf16* As1 = As0 + TARR;
        const bf16* As2 = As0 + 2 * TARR;
        const bf16* Bs0 = As0 + 3 * TARR;
        const bf16* Bs1 = As0 + 4 * TARR;
        const bf16* Bs2 = As0 + 5 * TARR;

#pragma unroll
        for (int kk = 0; kk < TBK / 16; kk++) {
            wmma::fragment<wmma::matrix_b, 16, 16, 16, bf16, wmma::col_major> b0[2], b1[2], b2[2];
#pragma unroll
            for (int j = 0; j < 2; j++) {
                wmma::load_matrix_sync(b0[j], Bs0 + (wn + j * 16) * TLD + kk * 16, TLD);
                wmma::load_matrix_sync(b1[j], Bs1 + (wn + j * 16) * TLD + kk * 16, TLD);
                wmma::load_matrix_sync(b2[j], Bs2 + (wn + j * 16) * TLD + kk * 16, TLD);
            }
#pragma unroll
            for (int ip = 0; ip < 2; ip++) {         // i-pairs: rows (2ip, 2ip+1)
                wmma::fragment<wmma::matrix_a, 16, 16, 16, bf16, wmma::row_major> a0[2], a1[2], a2[2];
#pragma unroll
                for (int di = 0; di < 2; di++) {
                    const int i = ip * 2 + di;
                    wmma::load_matrix_sync(a0[di], As0 + (wm + i * 16) * TLD + kk * 16, TLD);
                    wmma::load_matrix_sync(a1[di], As1 + (wm + i * 16) * TLD + kk * 16, TLD);
                    wmma::load_matrix_sync(a2[di], As2 + (wm + i * 16) * TLD + kk * 16, TLD);
                }
                // term-major ordering: 4 independent (di,j) mma per term,
                // so same-accumulator reuse distance is 4.
#pragma unroll
                for (int di = 0; di < 2; di++)
#pragma unroll
                    for (int j = 0; j < 2; j++)
                        wmma::mma_sync(ac0[ip * 2 + di][j], a0[di], b0[j], ac0[ip * 2 + di][j]);
#pragma unroll
                for (int di = 0; di < 2; di++)
#pragma unroll
                    for (int j = 0; j < 2; j++)
                        wmma::mma_sync(ac1[ip * 2 + di][j], a0[di], b1[j], ac1[ip * 2 + di][j]);
#pragma unroll
                for (int di = 0; di < 2; di++)
#pragma unroll
                    for (int j = 0; j < 2; j++)
                        wmma::mma_sync(ac1[ip * 2 + di][j], a1[di], b0[j], ac1[ip * 2 + di][j]);
#pragma unroll
                for (int di = 0; di < 2; di++)
#pragma unroll
                    for (int j = 0; j < 2; j++)
                        wmma::mma_sync(ac1[ip * 2 + di][j], a1[di], b1[j], ac1[ip * 2 + di][j]);
#pragma unroll
                for (int di = 0; di < 2; di++)
#pragma unroll
                    for (int j = 0; j < 2; j++)
                        wmma::mma_sync(ac1[ip * 2 + di][j], a0[di], b2[j], ac1[ip * 2 + di][j]);
#pragma unroll
                for (int di = 0; di < 2; di++)
#pragma unroll
                    for (int j = 0; j < 2; j++)
                        wmma::mma_sync(ac1[ip * 2 + di][j], a2[di], b0[j], ac1[ip * 2 + di][j]);
            }
        }
        __syncthreads();
    }

#pragma unroll
    for (int i = 0; i < 4; i++)
#pragma unroll
        for (int j = 0; j < 2; j++)
#pragma unroll
            for (int e = 0; e < ac0[i][j].num_elements; e++)
                ac0[i][j].x[e] += ac1[i][j].x[e];

    float* smf = (float*)sm;
    const int LDT = TBN + 4;
    __syncthreads();
#pragma unroll
    for (int i = 0; i < 4; i++)
#pragma unroll
        for (int j = 0; j < 2; j++)
            wmma::store_matrix_sync(smf + (wm + i * 16) * LDT + wn + j * 16,
                                    ac0[i][j], LDT, wmma::mem_row_major);
    __syncthreads();

    const int row = tid >> 1;
    const int ch = (tid & 1) * 64;
#pragma unroll
    for (int j = 0; j < 16; j++) {
        const int col = ch + j * 4;
        float4 v = *(const float4*)(smf + row * LDT + col);
        const int gc = bn + col;
        float b0 = bias1 ? __ldg(bias1 + gc + 0) : 0.0f;
        float b1 = bias1 ? __ldg(bias1 + gc + 1) : 0.0f;
        float b2 = bias1 ? __ldg(bias1 + gc + 2) : 0.0f;
        float b3 = bias1 ? __ldg(bias1 + gc + 3) : 0.0f;
        if (bias2) {
            b0 += __ldg(bias2 + gc + 0); b1 += __ldg(bias2 + gc + 1);
            b2 += __ldg(bias2 + gc + 2); b3 += __ldg(bias2 + gc + 3);
        }
        float4 o;
        o.x = alpha * v.x + b0; o.y = alpha * v.y + b1;
        o.z = alpha * v.z + b2; o.w = alpha * v.w + b3;
        *(float4*)(C + (long)(bm + row) * ldc + gc) = o;
    }
}

// ==================== prep / check kernels ==================================
__global__ void __launch_bounds__(256) r13_split3_kernel(
    const float* __restrict__ a, bf16* __restrict__ o0, bf16* __restrict__ o1,
    bf16* __restrict__ o2)
{
    long i = ((long)blockIdx.x * 256 + threadIdx.x) * 8;
    float4 v0 = *(const float4*)(a + i);
    float4 v1 = *(const float4*)(a + i + 4);
    float vv[8] = { v0.x, v0.y, v0.z, v0.w, v1.x, v1.y, v1.z, v1.w };
    __align__(16) bf16 q[8][3];
#pragma unroll
    for (int k = 0; k < 8; k++) r13_split3(vv[k], q[k]);
    __align__(16) bf16 t0[8], t1[8], t2[8];
#pragma unroll
    for (int k = 0; k < 8; k++) { t0[k]=q[k][0]; t1[k]=q[k][1]; t2[k]=q[k][2]; }
    *(uint4*)(o0 + i) = *(uint4*)t0;
    *(uint4*)(o1 + i) = *(uint4*)t1;
    *(uint4*)(o2 + i) = *(uint4*)t2;
}

__global__ void __launch_bounds__(256) r13_splitT3_kernel(
    const float* __restrict__ W, bf16* __restrict__ T0, bf16* __restrict__ T1,
    bf16* __restrict__ T2, int K, int N)
{
    __shared__ float tile[32][33];
    const int n0 = blockIdx.x * 32, k0 = blockIdx.y * 32;
    const int tx = threadIdx.x & 31, ty = threadIdx.x >> 5;
    for (int i = ty; i < 32; i += 8)
        tile[i][tx] = W[(long)(k0 + i) * N + n0 + tx];
    __syncthreads();
    for (int i = ty; i < 32; i += 8) {
        bf16 s[3];
        r13_split3(tile[tx][i], s);
        long o = (long)(n0 + i) * K + k0 + tx;
        T0[o] = s[0]; T1[o] = s[1]; T2[o] = s[2];
    }
}

__global__ void __launch_bounds__(256) r13_check_kernel(
    const float* __restrict__ f, const float* __restrict__ t, int* viol, long n4)
{
    long i = (long)blockIdx.x * 256 + threadIdx.x;
    if (i >= n4) return;
    float4 a = ((const float4*)f)[i];
    float4 b = ((const float4*)t)[i];
    int bad = 0;
    bad += (fabsf(a.x - b.x) > 5e-6f * fmaxf(fabsf(a.x), 1.0f));
    bad += (fabsf(a.y - b.y) > 5e-6f * fmaxf(fabsf(a.y), 1.0f));
    bad += (fabsf(a.z - b.z) > 5e-6f * fmaxf(fabsf(a.z), 1.0f));
    bad += (fabsf(a.w - b.w) > 5e-6f * fmaxf(fabsf(a.w), 1.0f));
    if (bad) atomicAdd(viol, bad);
}

__global__ void r13_setflag_kernel(int* flag, const int* viol) {
    *flag = (*viol == 0) ? 1 : 0;
}

// ==================== elementwise step kernels ==============================
__inline__ __device__ float r13_warpsum(float v) {
#pragma unroll
    for (int o = 16; o > 0; o >>= 1) v += __shfl_xor_sync(0xffffffffu, v, o);
    return v;
}

__global__ void __launch_bounds__(256) r13_step1_kernel(
    const float* __restrict__ pre, long ldp, float* __restrict__ rec,
    float* __restrict__ ctx, float* __restrict__ sfloat,
    bf16* __restrict__ s0_o, bf16* __restrict__ s1_o, bf16* __restrict__ s2_o,
    const float* __restrict__ gamma, const float* __restrict__ beta)
{
    const int row = blockIdx.x;
    const float* p = pre + (long)row * ldp;
    float* r = rec + (long)row * H_;
    float vals[8];
    float sum = 0.f, sumsq = 0.f;
#pragma unroll
    for (int i = 0; i < 8; i++) {
        int h = threadIdx.x + i * 256;
        float u = tanhf(p[h]);
        float nr = 0.9f * r[h] + 0.1f * u;
        r[h] = nr; vals[i] = nr;
        sum += nr; sumsq += nr * nr;
    }
    float w1 = r13_warpsum(sum), w2 = r13_warpsum(sumsq);
    __shared__ float sh[16];
    int warp = threadIdx.x >> 5, lane = threadIdx.x & 31;
    if (lane == 0) { sh[warp] = w1; sh[8 + warp] = w2; }
    __syncthreads();
    if (threadIdx.x == 0) {
        float a = 0.f, b = 0.f;
#pragma unroll
        for (int i = 0; i < 8; i++) { a += sh[i]; b += sh[8 + i]; }
        sh[0] = a; sh[8] = b;
    }
    __syncthreads();
    const float mean = sh[0] * (1.0f / H_);
    const float var  = sh[8] * (1.0f / H_) - mean * mean;
    const float inv  = rsqrtf(var + 1e-5f);
#pragma unroll
    for (int i = 0; i < 8; i++) {
        int h = threadIdx.x + i * 256;
        float c = (vals[i] - mean) * inv * gamma[h] + beta[h];
        long o = (long)row * H_ + h;
        ctx[o] = c;
        float s = c + vals[i];
        sfloat[o] = s;
        bf16 q[3]; r13_split3(s, q);
        s0_o[o] = q[0]; s1_o[o] = q[1]; s2_o[o] = q[2];
    }
}

__global__ void __launch_bounds__(256) r13_step2_kernel(
    const float* __restrict__ pre, const float* __restrict__ ctx,
    const float* __restrict__ rec, float* __restrict__ gfloat,
    bf16* __restrict__ g0_o, bf16* __restrict__ g1_o, bf16* __restrict__ g2_o)
{
    long i = ((long)blockIdx.x * 256 + threadIdx.x) * 4;
    float4 p = *(const float4*)(pre + i);
    float4 c = *(const float4*)(ctx + i);
    float4 r = *(const float4*)(rec + i);
    float pv[4] = { p.x, p.y, p.z, p.w };
    float cv[4] = { c.x, c.y, c.z, c.w };
    float rv[4] = { r.x, r.y, r.z, r.w };
    float ov[4];
    __align__(8) bf16 q0[4], q1[4], q2[4];
#pragma unroll
    for (int k = 0; k < 4; k++) {
        float g = 1.0f / (1.0f + expf(-pv[k]));
        ov[k] = g * cv[k] + (1.0f - g) * rv[k];
        bf16 q[3]; r13_split3(ov[k], q);
        q0[k] = q[0]; q1[k] = q[1]; q2[k] = q[2];
    }
    *(float4*)(gfloat + i) = make_float4(ov[0], ov[1], ov[2], ov[3]);
    *(uint2*)(g0_o + i) = *(uint2*)q0;
    *(uint2*)(g1_o + i) = *(uint2*)q1;
    *(uint2*)(g2_o + i) = *(uint2*)q2;
}

// step3: LIF + near-threshold fp64 refinement (8-way unrolled) + double-buffer
__global__ void __launch_bounds__(256) r13_step3_kernel(
    const float* __restrict__ cur, const float* __restrict__ attr_in,
    float* __restrict__ attr_out,
    bf16* __restrict__ a0_o, bf16* __restrict__ a1_o, bf16* __restrict__ a2_o,
    float* __restrict__ spk,
    const float* __restrict__ gf,
    const float* __restrict__ Wenc, const float* __restrict__ benc,
    const float* __restrict__ Wrec, const float* __restrict__ brec)
{
    long i = ((long)blockIdx.x * 256 + threadIdx.x) * 4;
    float4 c = *(const float4*)(cur + i);
    float4 a = *(const float4*)(attr_in + i);
    float4 sp = *(float4*)(spk + i);
    float cv[4] = { c.x, c.y, c.z, c.w };
    float av[4] = { a.x, a.y, a.z, a.w };
    float sv[4] = { sp.x, sp.y, sp.z, sp.w };
    __align__(8) bf16 q0[4], q1[4], q2[4];
    const long row = i / H_;
    const int  hb  = (int)(i % H_);
#pragma unroll
    for (int k = 0; k < 4; k++) {
        float v = av[k] + (cv[k] - av[k]) * 0.5f;
        if (fabsf(v - 1.0f) < 1e-4f) {
            const int h = hb + k;
            const float* grow = gf + row * H_;
            const float* arow = attr_in + row * H_;
            // 8 independent fp64 accumulation chains (chain len 512, not 8192)
            double d0 = 0.0, d1 = 0.0, d2 = 0.0, d3 = 0.0;
            double d4 = 0.0, d5 = 0.0, d6 = 0.0, d7 = 0.0;
            for (int kk = 0; kk < H_; kk += 4) {
                d0 += (double)grow[kk + 0] * (double)Wenc[(long)(kk + 0) * H_ + h];
                d1 += (double)grow[kk + 1] * (double)Wenc[(long)(kk + 1) * H_ + h];
                d2 += (double)grow[kk + 2] * (double)Wenc[(long)(kk + 2) * H_ + h];
                d3 += (double)grow[kk + 3] * (double)Wenc[(long)(kk + 3) * H_ + h];
                d4 += (double)arow[kk + 0] * (double)Wrec[(long)(kk + 0) * H_ + h];
                d5 += (double)arow[kk + 1] * (double)Wrec[(long)(kk + 1) * H_ + h];
                d6 += (double)arow[kk + 2] * (double)Wrec[(long)(kk + 2) * H_ + h];
                d7 += (double)arow[kk + 3] * (double)Wrec[(long)(kk + 3) * H_ + h];
            }
            double acc = (double)benc[h] + (double)brec[h]
                       + ((d0 + d1) + (d2 + d3)) + ((d4 + d5) + (d6 + d7));
            v = av[k] + ((float)acc - av[k]) * 0.5f;
        }
        float s = (v > 1.0f) ? 1.0f : 0.0f;
        av[k] = v - s; sv[k] += s;
        bf16 q[3]; r13_split3(av[k], q);
        q0[k] = q[0]; q1[k] = q[1]; q2[k] = q[2];
    }
    *(float4*)(attr_out + i) = make_float4(av[0], av[1], av[2], av[3]);
    *(float4*)(spk + i)      = make_float4(sv[0], sv[1], sv[2], sv[3]);
    *(uint2*)(a0_o + i) = *(uint2*)q0;
    *(uint2*)(a1_o + i) = *(uint2*)q1;
    *(uint2*)(a2_o + i) = *(uint2*)q2;
}

__global__ void __launch_bounds__(256) r13_init_kernel(
    float* __restrict__ rec, float* __restrict__ attr, float* __restrict__ spk,
    bf16* __restrict__ a0, bf16* __restrict__ a1, bf16* __restrict__ a2, int* viol)
{
    long i = (long)blockIdx.x * 256 + threadIdx.x;
    if (i == 0) *viol = 0;
    float4 z = make_float4(0.f, 0.f, 0.f, 0.f);
    ((float4*)rec)[i] = z; ((float4*)attr)[i] = z; ((float4*)spk)[i] = z;
    uint2 z2 = make_uint2(0u, 0u);
    ((uint2*)a0)[i] = z2; ((uint2*)a1)[i] = z2; ((uint2*)a2)[i] = z2;
}

__global__ void __launch_bounds__(256) r13_tail_kernel(
    const float* __restrict__ rec, const float* __restrict__ attr, float* __restrict__ out)
{
    long i = (long)blockIdx.x * 256 + threadIdx.x;
    ((float4*)out)[i] = ((const float4*)rec)[i];
    ((float4*)(out + (long)B_ * H_))[i] = ((const float4*)attr)[i];
}

// ==================== launch =================================================
#define GETSYM(var, sym) cudaGetSymbolAddress((void**)&var, sym)

extern "C" void kernel_launch(void* const* d_in, const int* in_sizes, int n_in,
                              void* d_out, int out_size)
{
    const float* x    = (const float*)d_in[0];
    const float* Wp   = (const float*)d_in[1];
    const float* bp   = (const float*)d_in[2];
    const float* Wfc  = (const float*)d_in[3];
    const float* bfc  = (const float*)d_in[4];
    const float* gamma= (const float*)d_in[5];
    const float* beta = (const float*)d_in[6];
    const float* Wg   = (const float*)d_in[7];
    const float* bg   = (const float*)d_in[8];
    const float* Wenc = (const float*)d_in[9];
    const float* benc = (const float*)d_in[10];
    const float* Wrec = (const float*)d_in[11];
    const float* brec = (const float*)d_in[12];
    const float* Wro  = (const float*)d_in[13];
    const float* bro  = (const float*)d_in[14];
    float* out = (float*)d_out;

    int *flag, *viol;
    float *inp, *preall, *pre, *sf, *gf, *ctx, *rec, *attrA, *attrB, *spk, *testF, *testT;
    GETSYM(flag, r13_flag);   GETSYM(viol, r13_viol);
    GETSYM(inp, r13_inp);     GETSYM(preall, r13_preall);
    GETSYM(pre, r13_pre);
    GETSYM(sf, r13_sf);       GETSYM(gf, r13_gf);
    GETSYM(ctx, r13_ctx);     GETSYM(rec, r13_rec);
    GETSYM(attrA, r13_attrA); GETSYM(attrB, r13_attrB);
    GETSYM(spk, r13_spk);
    GETSYM(testF, r13_testF); GETSYM(testT, r13_testT);

    bf16 *xb0, *xb1, *xb2, *ib0, *ib1, *ib2;
    bf16 *Wp0, *Wp1, *Wp2, *Wfc0, *Wfc1, *Wfc2, *Wg0, *Wg1, *Wg2;
    bf16 *We0, *We1, *We2, *Wr0, *Wr1, *Wr2, *Wo0, *Wo1, *Wo2;
    bf16 *sb0, *sb1, *sb2, *gb0, *gb1, *gb2, *ab0, *ab1, *ab2, *pb0, *pb1, *pb2;
    GETSYM(xb0, r13_xb0); GETSYM(xb1, r13_xb1); GETSYM(xb2, r13_xb2);
    GETSYM(ib0, r13_ib0); GETSYM(ib1, r13_ib1); GETSYM(ib2, r13_ib2);
    GETSYM(Wp0, r13_Wp0); GETSYM(Wp1, r13_Wp1); GETSYM(Wp2, r13_Wp2);
    GETSYM(Wfc0, r13_Wfc0); GETSYM(Wfc1, r13_Wfc1); GETSYM(Wfc2, r13_Wfc2);
    GETSYM(Wg0, r13_Wg0); GETSYM(Wg1, r13_Wg1); GETSYM(Wg2, r13_Wg2);
    GETSYM(We0, r13_We0); GETSYM(We1, r13_We1); GETSYM(We2, r13_We2);
    GETSYM(Wr0, r13_Wr0); GETSYM(Wr1, r13_Wr1); GETSYM(Wr2, r13_Wr2);
    GETSYM(Wo0, r13_Wo0); GETSYM(Wo1, r13_Wo1); GETSYM(Wo2, r13_Wo2);
    GETSYM(sb0, r13_sb0); GETSYM(sb1, r13_sb1); GETSYM(sb2, r13_sb2);
    GETSYM(gb0, r13_gb0); GETSYM(gb1, r13_gb1); GETSYM(gb2, r13_gb2);
    GETSYM(ab0, r13_ab0); GETSYM(ab1, r13_ab1); GETSYM(ab2, r13_ab2);
    GETSYM(pb0, r13_pb0); GETSYM(pb1, r13_pb1); GETSYM(pb2, r13_pb2);

    cudaFuncSetAttribute(r13_tgemm, cudaFuncAttributeMaxDynamicSharedMemorySize, TSMEM);

    const int EW = (B_ * H_ / 4) / 256;

    r13_init_kernel<<<EW, 256>>>(rec, attrA, spk, ab0, ab1, ab2, viol);

    // splits
    r13_split3_kernel<<<(B_ * T_ * D_ / 8) / 256, 256>>>(x, xb0, xb1, xb2);
    r13_splitT3_kernel<<<dim3(H_ / 32, D_ / 32), 256>>>(Wp, Wp0, Wp1, Wp2, D_, H_);
    r13_splitT3_kernel<<<dim3(H_ / 32, H_ / 32), 256>>>(Wfc, Wfc0, Wfc1, Wfc2, H_, H_);
    r13_splitT3_kernel<<<dim3(H_ / 32, H_ / 32), 256>>>(Wg, Wg0, Wg1, Wg2, H_, H_);
    r13_splitT3_kernel<<<dim3(H_ / 32, H_ / 32), 256>>>(Wenc, We0, We1, We2, H_, H_);
    r13_splitT3_kernel<<<dim3(H_ / 32, H_ / 32), 256>>>(Wrec, Wr0, Wr1, Wr2, H_, H_);
    r13_splitT3_kernel<<<dim3(O_ / 32, H_ / 32), 256>>>(Wro, Wo0, Wo1, Wo2, H_, O_);

    // probe
    r13_sgemm<<<dim3(H_ / 128, 1), 256>>>(nullptr, x, D_, Wp, nullptr, 0, nullptr,
                                          bp, nullptr, testF, H_, 128, H_, D_, 1.0f);
    {
        R13P p = { xb0, xb1, xb2, D_, Wp0, Wp1, Wp2, D_ };
        r13_tgemm<<<dim3(H_ / TBN, 1), 256, TSMEM>>>(p, p, 1, nullptr,
                                                     bp, nullptr, testT, H_, 1.0f);
    }
    r13_check_kernel<<<(128 * H_ / 4 + 255) / 256, 256>>>(testF, testT, viol, 128 * H_ / 4);
    r13_setflag_kernel<<<1, 1>>>(flag, viol);

    // input projection (dual)
    r13_sgemm<<<dim3(H_ / 128, (B_ * T_) / 128), 256>>>(flag, x, D_, Wp,
        nullptr, 0, nullptr, bp, nullptr, inp, H_, B_ * T_, H_, D_, 1.0f);
    {
        R13P p = { xb0, xb1, xb2, D_, Wp0, Wp1, Wp2, D_ };
        r13_tgemm<<<dim3(H_ / TBN, (B_ * T_) / TBM), 256, TSMEM>>>(p, p, 1, flag,
                                                                   bp, nullptr, inp, H_, 1.0f);
    }
    r13_split3_kernel<<<(B_ * T_ * H_ / 8) / 256, 256>>>(inp, ib0, ib1, ib2);

    // batched GEMM1 for ALL timesteps (dual)
    r13_sgemm<<<dim3(H_ / 128, (B_ * T_) / 128), 256>>>(flag, inp, H_, Wfc,
        nullptr, 0, nullptr, bfc, nullptr, preall, H_, B_ * T_, H_, H_, 1.0f);
    {
        R13P p = { ib0, ib1, ib2, H_, Wfc0, Wfc1, Wfc2, H_ };
        r13_tgemm<<<dim3(H_ / TBN, (B_ * T_) / TBM), 256, TSMEM>>>(p, p, 1, flag,
                                                                   bfc, nullptr, preall, H_, 1.0f);
    }

    const dim3 gF(H_ / 128, B_ / 128);
    const dim3 gT(H_ / TBN, B_ / TBM);
    for (int t = 0; t < T_; t++) {
        float* attr_in  = (t & 1) ? attrB : attrA;
        float* attr_out = (t & 1) ? attrA : attrB;
        r13_step1_kernel<<<B_, 256>>>(preall + (long)t * H_, (long)T_ * H_,
                                      rec, ctx, sf, sb0, sb1, sb2, gamma, beta);
        // GEMM2 (dual)
        r13_sgemm<<<gF, 256>>>(flag, sf, H_, Wg, nullptr, 0, nullptr,
                               bg, nullptr, pre, H_, B_, H_, H_, 1.0f);
        {
            R13P p = { sb0, sb1, sb2, H_, Wg0, Wg1, Wg2, H_ };
            r13_tgemm<<<gT, 256, TSMEM>>>(p, p, 1, flag, bg, nullptr, pre, H_, 1.0f);
        }
        r13_step2_kernel<<<EW, 256>>>(pre, ctx, rec, gf, gb0, gb1, gb2);
        // GEMM3 dual-pass (dual)
        r13_sgemm<<<gF, 256>>>(flag, gf, H_, Wenc, attr_in, H_, Wrec,
                               benc, brec, pre, H_, B_, H_, H_, 1.0f);
        {
            R13P pa = { gb0, gb1, gb2, H_, We0, We1, We2, H_ };
            R13P pb = { ab0, ab1, ab2, H_, Wr0, Wr1, Wr2, H_ };
            r13_tgemm<<<gT, 256, TSMEM>>>(pa, pb, 2, flag, benc, brec, pre, H_, 1.0f);
        }
        r13_step3_kernel<<<EW, 256>>>(pre, attr_in, attr_out,
                                      ab0, ab1, ab2, spk,
                                      gf, Wenc, benc, Wrec, brec);
    }

    // readout (dual)
    r13_split3_kernel<<<(B_ * H_ / 8) / 256, 256>>>(spk, pb0, pb1, pb2);
    r13_sgemm<<<dim3(O_ / 128, B_ / 128), 256>>>(flag, spk, H_, Wro,
        nullptr, 0, nullptr, bro, nullptr, out, O_, B_, O_, H_, 1.0f / 16.0f);
    {
        R13P p = { pb0, pb1, pb2, H_, Wo0, Wo1, Wo2, H_ };
        r13_tgemm<<<dim3(O_ / TBN, B_ / TBM), 256, TSMEM>>>(p, p, 1, flag,
                                                            bro, nullptr, out, O_, 1.0f / 16.0f);
    }
    r13_tail_kernel<<<EW, 256>>>(rec, attrA, out + (long)B_ * O_);
}

// round 14
// speedup vs baseline: 1.3785x; 1.3785x over previous
#include <cuda_runtime.h>
#include <math.h>
#include <stdint.h>

#define B_ 1024
#define T_ 16
#define D_ 1024
#define H_ 2048
#define O_ 1024

// ==================== device globals ========================================
__device__ float r14_Wfused[D_ * H_];
__device__ float r14_bfused[H_];
__device__ float r14_preall[B_ * T_ * H_];
__device__ float r14_pre[B_ * H_];
__device__ float r14_sf[B_ * H_];
__device__ float r14_gf[B_ * H_];
__device__ float r14_ctx[B_ * H_], r14_rec[B_ * H_];
__device__ float r14_attrA[B_ * H_], r14_attrB[B_ * H_];
__device__ float r14_spk[B_ * H_];

// ==================== fp32 SGEMM (proven R1 engine) =========================
// C = alpha * (A1@B1 [+ A2@B2]) + bias1 (+ bias2)
// A row-major [M, lda]; B row-major [K, N] contiguous; C row-major [M, ldc].
__global__ void __launch_bounds__(256) r14_sgemm(
    const float* __restrict__ A1, int lda1, const float* __restrict__ B1,
    const float* __restrict__ A2, int lda2, const float* __restrict__ B2,
    const float* __restrict__ bias1, const float* __restrict__ bias2,
    float* __restrict__ C, int ldc, int M, int N, int K, float alpha)
{
    const int BM = 128, BN = 128, BK = 16;
    __shared__ float As[BK][BM];
    __shared__ float Bs[BK][BN];
    const int bm = blockIdx.y * BM, bn = blockIdx.x * BN;
    const int tid = threadIdx.x, tr = tid / 16, tc = tid % 16;
    const int a_r = tid / 4, a_c = (tid % 4) * 4;
    const int b_r = tid / 32, b_c = (tid % 32) * 4;

    float acc[8][8];
#pragma unroll
    for (int i = 0; i < 8; i++)
#pragma unroll
        for (int j = 0; j < 8; j++) acc[i][j] = 0.0f;

    const int npass = (A2 != nullptr) ? 2 : 1;
    for (int pass = 0; pass < npass; pass++) {
        const float* A  = pass ? A2 : A1;
        const float* Bm = pass ? B2 : B1;
        const int lda   = pass ? lda2 : lda1;
        for (int k0 = 0; k0 < K; k0 += BK) {
#pragma unroll
            for (int i = 0; i < 2; i++) {
                int r = a_r + i * 64;
                float4 v = *(const float4*)(A + (long)(bm + r) * lda + k0 + a_c);
                As[a_c + 0][r] = v.x; As[a_c + 1][r] = v.y;
                As[a_c + 2][r] = v.z; As[a_c + 3][r] = v.w;
            }
#pragma unroll
            for (int i = 0; i < 2; i++) {
                int r = b_r + i * 8;
                float4 v = *(const float4*)(Bm + (long)(k0 + r) * N + bn + b_c);
                *(float4*)&Bs[r][b_c] = v;
            }
            __syncthreads();
#pragma unroll
            for (int kk = 0; kk < BK; kk++) {
                float4 a0 = *(const float4*)&As[kk][tr * 8];
                float4 a1 = *(const float4*)&As[kk][tr * 8 + 4];
                float4 b0 = *(const float4*)&Bs[kk][tc * 8];
                float4 b1 = *(const float4*)&Bs[kk][tc * 8 + 4];
                float a[8] = {a0.x, a0.y, a0.z, a0.w, a1.x, a1.y, a1.z, a1.w};
                float b[8] = {b0.x, b0.y, b0.z, b0.w, b1.x, b1.y, b1.z, b1.w};
#pragma unroll
                for (int i = 0; i < 8; i++)
#pragma unroll
                    for (int j = 0; j < 8; j++)
                        acc[i][j] = fmaf(a[i], b[j], acc[i][j]);
            }
            __syncthreads();
        }
    }
    const int row0 = bm + tr * 8, col0 = bn + tc * 8;
    float bias[8];
#pragma unroll
    for (int j = 0; j < 8; j++) {
        float v = bias1 ? bias1[col0 + j] : 0.0f;
        if (bias2) v += bias2[col0 + j];
        bias[j] = v;
    }
#pragma unroll
    for (int i = 0; i < 8; i++) {
        float4 o0, o1;
        o0.x = alpha * acc[i][0] + bias[0]; o0.y = alpha * acc[i][1] + bias[1];
        o0.z = alpha * acc[i][2] + bias[2]; o0.w = alpha * acc[i][3] + bias[3];
        o1.x = alpha * acc[i][4] + bias[4]; o1.y = alpha * acc[i][5] + bias[5];
        o1.z = alpha * acc[i][6] + bias[6]; o1.w = alpha * acc[i][7] + bias[7];
        *(float4*)(C + (long)(row0 + i) * ldc + col0)     = o0;
        *(float4*)(C + (long)(row0 + i) * ldc + col0 + 4) = o1;
    }
}

// bfused[n] = bp @ Wfc + bfc
__global__ void __launch_bounds__(256) r14_bfused_kernel(
    const float* __restrict__ bp, const float* __restrict__ Wfc,
    const float* __restrict__ bfc, float* __restrict__ out)
{
    const int n = blockIdx.x * 256 + threadIdx.x;
    float a0 = 0.f, a1 = 0.f, a2 = 0.f, a3 = 0.f;
    for (int k = 0; k < H_; k += 4) {
        a0 = fmaf(bp[k + 0], Wfc[(long)(k + 0) * H_ + n], a0);
        a1 = fmaf(bp[k + 1], Wfc[(long)(k + 1) * H_ + n], a1);
        a2 = fmaf(bp[k + 2], Wfc[(long)(k + 2) * H_ + n], a2);
        a3 = fmaf(bp[k + 3], Wfc[(long)(k + 3) * H_ + n], a3);
    }
    out[n] = ((a0 + a1) + (a2 + a3)) + bfc[n];
}

// ==================== elementwise step kernels ==============================
__inline__ __device__ float r14_warpsum(float v) {
#pragma unroll
    for (int o = 16; o > 0; o >>= 1) v += __shfl_xor_sync(0xffffffffu, v, o);
    return v;
}

__global__ void __launch_bounds__(256) r14_step1_kernel(
    const float* __restrict__ pre, long ldp, float* __restrict__ rec,
    float* __restrict__ ctx, float* __restrict__ s,
    const float* __restrict__ gamma, const float* __restrict__ beta)
{
    const int row = blockIdx.x;
    const float* p = pre + (long)row * ldp;
    float* r = rec + (long)row * H_;
    float vals[8];
    float sum = 0.f, sumsq = 0.f;
#pragma unroll
    for (int i = 0; i < 8; i++) {
        int h = threadIdx.x + i * 256;
        float u = tanhf(p[h]);
        float nr = 0.9f * r[h] + 0.1f * u;
        r[h] = nr; vals[i] = nr;
        sum += nr; sumsq += nr * nr;
    }
    float w1 = r14_warpsum(sum), w2 = r14_warpsum(sumsq);
    __shared__ float sh[16];
    int warp = threadIdx.x >> 5, lane = threadIdx.x & 31;
    if (lane == 0) { sh[warp] = w1; sh[8 + warp] = w2; }
    __syncthreads();
    if (threadIdx.x == 0) {
        float a = 0.f, b = 0.f;
#pragma unroll
        for (int i = 0; i < 8; i++) { a += sh[i]; b += sh[8 + i]; }
        sh[0] = a; sh[8] = b;
    }
    __syncthreads();
    const float mean = sh[0] * (1.0f / H_);
    const float var  = sh[8] * (1.0f / H_) - mean * mean;
    const float inv  = rsqrtf(var + 1e-5f);
#pragma unroll
    for (int i = 0; i < 8; i++) {
        int h = threadIdx.x + i * 256;
        float c = (vals[i] - mean) * inv * gamma[h] + beta[h];
        long o = (long)row * H_ + h;
        ctx[o] = c;
        s[o] = c + vals[i];
    }
}

__global__ void __launch_bounds__(256) r14_step2_kernel(
    const float* __restrict__ pre, const float* __restrict__ ctx,
    const float* __restrict__ rec, float* __restrict__ gated)
{
    long i = (long)blockIdx.x * blockDim.x + threadIdx.x;
    const float4 p = ((const float4*)pre)[i];
    const float4 c = ((const float4*)ctx)[i];
    const float4 r = ((const float4*)rec)[i];
    float4 o;
    float g;
    g = 1.0f / (1.0f + expf(-p.x)); o.x = g * c.x + (1.0f - g) * r.x;
    g = 1.0f / (1.0f + expf(-p.y)); o.y = g * c.y + (1.0f - g) * r.y;
    g = 1.0f / (1.0f + expf(-p.z)); o.z = g * c.z + (1.0f - g) * r.z;
    g = 1.0f / (1.0f + expf(-p.w)); o.w = g * c.w + (1.0f - g) * r.w;
    ((float4*)gated)[i] = o;
}

// step3: LIF + near-threshold fp64 refinement + attr double-buffer
__global__ void __launch_bounds__(256) r14_step3_kernel(
    const float* __restrict__ cur, const float* __restrict__ attr_in,
    float* __restrict__ attr_out, float* __restrict__ spk,
    const float* __restrict__ gf,
    const float* __restrict__ Wenc, const float* __restrict__ benc,
    const float* __restrict__ Wrec, const float* __restrict__ brec)
{
    long i = ((long)blockIdx.x * 256 + threadIdx.x) * 4;
    float4 c = *(const float4*)(cur + i);
    float4 a = *(const float4*)(attr_in + i);
    float4 sp = *(float4*)(spk + i);
    float cv[4] = { c.x, c.y, c.z, c.w };
    float av[4] = { a.x, a.y, a.z, a.w };
    float sv[4] = { sp.x, sp.y, sp.z, sp.w };
    const long row = i / H_;
    const int  hb  = (int)(i % H_);
#pragma unroll
    for (int k = 0; k < 4; k++) {
        float v = av[k] + (cv[k] - av[k]) * 0.5f;
        if (fabsf(v - 1.0f) < 1e-4f) {
            const int h = hb + k;
            const float* grow = gf + row * H_;
            const float* arow = attr_in + row * H_;
            double d0 = 0.0, d1 = 0.0, d2 = 0.0, d3 = 0.0;
            double d4 = 0.0, d5 = 0.0, d6 = 0.0, d7 = 0.0;
            for (int kk = 0; kk < H_; kk += 4) {
                d0 += (double)grow[kk + 0] * (double)Wenc[(long)(kk + 0) * H_ + h];
                d1 += (double)grow[kk + 1] * (double)Wenc[(long)(kk + 1) * H_ + h];
                d2 += (double)grow[kk + 2] * (double)Wenc[(long)(kk + 2) * H_ + h];
                d3 += (double)grow[kk + 3] * (double)Wenc[(long)(kk + 3) * H_ + h];
                d4 += (double)arow[kk + 0] * (double)Wrec[(long)(kk + 0) * H_ + h];
                d5 += (double)arow[kk + 1] * (double)Wrec[(long)(kk + 1) * H_ + h];
                d6 += (double)arow[kk + 2] * (double)Wrec[(long)(kk + 2) * H_ + h];
                d7 += (double)arow[kk + 3] * (double)Wrec[(long)(kk + 3) * H_ + h];
            }
            double acc = (double)benc[h] + (double)brec[h]
                       + ((d0 + d1) + (d2 + d3)) + ((d4 + d5) + (d6 + d7));
            v = av[k] + ((float)acc - av[k]) * 0.5f;
        }
        float s = (v > 1.0f) ? 1.0f : 0.0f;
        av[k] = v - s; sv[k] += s;
    }
    *(float4*)(attr_out + i) = make_float4(av[0], av[1], av[2], av[3]);
    *(float4*)(spk + i)      = make_float4(sv[0], sv[1], sv[2], sv[3]);
}

__global__ void __launch_bounds__(256) r14_init_kernel(
    float* __restrict__ rec, float* __restrict__ attr, float* __restrict__ spk)
{
    long i = (long)blockIdx.x * blockDim.x + threadIdx.x;
    float4 z = make_float4(0.f, 0.f, 0.f, 0.f);
    ((float4*)rec)[i] = z; ((float4*)attr)[i] = z; ((float4*)spk)[i] = z;
}

__global__ void __launch_bounds__(256) r14_tail_kernel(
    const float* __restrict__ rec, const float* __restrict__ attr, float* __restrict__ out)
{
    long i = (long)blockIdx.x * blockDim.x + threadIdx.x;
    ((float4*)out)[i] = ((const float4*)rec)[i];
    ((float4*)(out + (long)B_ * H_))[i] = ((const float4*)attr)[i];
}

// ==================== launch =================================================
#define GETSYM(var, sym) cudaGetSymbolAddress((void**)&var, sym)

extern "C" void kernel_launch(void* const* d_in, const int* in_sizes, int n_in,
                              void* d_out, int out_size)
{
    const float* x    = (const float*)d_in[0];
    const float* Wp   = (const float*)d_in[1];
    const float* bp   = (const float*)d_in[2];
    const float* Wfc  = (const float*)d_in[3];
    const float* bfc  = (const float*)d_in[4];
    const float* gamma= (const float*)d_in[5];
    const float* beta = (const float*)d_in[6];
    const float* Wg   = (const float*)d_in[7];
    const float* bg   = (const float*)d_in[8];
    const float* Wenc = (const float*)d_in[9];
    const float* benc = (const float*)d_in[10];
    const float* Wrec = (const float*)d_in[11];
    const float* brec = (const float*)d_in[12];
    const float* Wro  = (const float*)d_in[13];
    const float* bro  = (const float*)d_in[14];
    float* out = (float*)d_out;

    float *Wfused, *bfused, *preall, *pre, *sf, *gf, *ctx, *rec, *attrA, *attrB, *spk;
    GETSYM(Wfused, r14_Wfused); GETSYM(bfused, r14_bfused);
    GETSYM(preall, r14_preall); GETSYM(pre, r14_pre);
    GETSYM(sf, r14_sf);         GETSYM(gf, r14_gf);
    GETSYM(ctx, r14_ctx);       GETSYM(rec, r14_rec);
    GETSYM(attrA, r14_attrA);   GETSYM(attrB, r14_attrB);
    GETSYM(spk, r14_spk);

    const int EW = (B_ * H_ / 4) / 256;  // 2048 blocks

    r14_init_kernel<<<EW, 256>>>(rec, attrA, spk);

    // fold: Wfused = Wp @ Wfc   (M=D, N=H, K=H)
    r14_sgemm<<<dim3(H_ / 128, D_ / 128), 256>>>(
        Wp, H_, Wfc, nullptr, 0, nullptr,
        nullptr, nullptr, Wfused, H_, D_, H_, H_, 1.0f);
    // bfused = bp @ Wfc + bfc
    r14_bfused_kernel<<<H_ / 256, 256>>>(bp, Wfc, bfc, bfused);

    // batched pre-activation for ALL timesteps: preall = x @ Wfused + bfused
    // (M = B*T, N = H, K = D)
    r14_sgemm<<<dim3(H_ / 128, (B_ * T_) / 128), 256>>>(
        x, D_, Wfused, nullptr, 0, nullptr,
        bfused, nullptr, preall, H_, B_ * T_, H_, D_, 1.0f);

    const dim3 gstep(H_ / 128, B_ / 128);  // (16, 8)
    for (int t = 0; t < T_; t++) {
        float* attr_in  = (t & 1) ? attrB : attrA;
        float* attr_out = (t & 1) ? attrA : attrB;
        // tanh + rec update + LayerNorm + s
        r14_step1_kernel<<<B_, 256>>>(preall + (long)t * H_, (long)T_ * H_,
                                      rec, ctx, sf, gamma, beta);
        // GEMM2: pre = s @ Wg + bg
        r14_sgemm<<<gstep, 256>>>(sf, H_, Wg, nullptr, 0, nullptr,
                                  bg, nullptr, pre, H_, B_, H_, H_, 1.0f);
        // gate
        r14_step2_kernel<<<EW, 256>>>(pre, ctx, rec, gf);
        // GEMM3 dual: pre = gated @ Wenc + attr @ Wrec + benc + brec
        r14_sgemm<<<gstep, 256>>>(gf, H_, Wenc, attr_in, H_, Wrec,
                                  benc, brec, pre, H_, B_, H_, H_, 1.0f);
        // LIF + refine + spike accumulation
        r14_step3_kernel<<<EW, 256>>>(pre, attr_in, attr_out, spk,
                                      gf, Wenc, benc, Wrec, brec);
    }

    // readout: out = (spk/16) @ Wro + bro
    r14_sgemm<<<dim3(O_ / 128, B_ / 128), 256>>>(
        spk, H_, Wro, nullptr, 0, nullptr,
        bro, nullptr, out, O_, B_, O_, H_, 1.0f / 16.0f);
    // after 16 steps final attr is in attrA
    r14_tail_kernel<<<EW, 256>>>(rec, attrA, out + (long)B_ * O_);
}

// round 15
// speedup vs baseline: 1.9699x; 1.4291x over previous
#include <cuda_runtime.h>
#include <math.h>
#include <stdint.h>

#define B_ 1024
#define T_ 16
#define D_ 1024
#define H_ 2048
#define O_ 1024
#define LIST_MAX (1 << 20)

// ==================== device globals ========================================
__device__ float r15_Wfused[D_ * H_];
__device__ float r15_bfused[H_];
__device__ float r15_WencT[H_ * H_], r15_WrecT[H_ * H_];
__device__ float r15_preall[B_ * T_ * H_];
__device__ float r15_pre[B_ * H_];
__device__ float r15_sf[B_ * H_];
__device__ float r15_gf[B_ * H_];
__device__ float r15_ctx[B_ * H_], r15_rec[B_ * H_];
__device__ float r15_attrA[B_ * H_], r15_attrB[B_ * H_];
__device__ float r15_spk[B_ * H_];
__device__ int   r15_cnt[T_];
__device__ int   r15_list[LIST_MAX];

// ==================== fp32 SGEMM (proven R1 engine) =========================
__global__ void __launch_bounds__(256) r15_sgemm(
    const float* __restrict__ A1, int lda1, const float* __restrict__ B1,
    const float* __restrict__ A2, int lda2, const float* __restrict__ B2,
    const float* __restrict__ bias1, const float* __restrict__ bias2,
    float* __restrict__ C, int ldc, int M, int N, int K, float alpha)
{
    const int BM = 128, BN = 128, BK = 16;
    __shared__ float As[BK][BM];
    __shared__ float Bs[BK][BN];
    const int bm = blockIdx.y * BM, bn = blockIdx.x * BN;
    const int tid = threadIdx.x, tr = tid / 16, tc = tid % 16;
    const int a_r = tid / 4, a_c = (tid % 4) * 4;
    const int b_r = tid / 32, b_c = (tid % 32) * 4;

    float acc[8][8];
#pragma unroll
    for (int i = 0; i < 8; i++)
#pragma unroll
        for (int j = 0; j < 8; j++) acc[i][j] = 0.0f;

    const int npass = (A2 != nullptr) ? 2 : 1;
    for (int pass = 0; pass < npass; pass++) {
        const float* A  = pass ? A2 : A1;
        const float* Bm = pass ? B2 : B1;
        const int lda   = pass ? lda2 : lda1;
        for (int k0 = 0; k0 < K; k0 += BK) {
#pragma unroll
            for (int i = 0; i < 2; i++) {
                int r = a_r + i * 64;
                float4 v = *(const float4*)(A + (long)(bm + r) * lda + k0 + a_c);
                As[a_c + 0][r] = v.x; As[a_c + 1][r] = v.y;
                As[a_c + 2][r] = v.z; As[a_c + 3][r] = v.w;
            }
#pragma unroll
            for (int i = 0; i < 2; i++) {
                int r = b_r + i * 8;
                float4 v = *(const float4*)(Bm + (long)(k0 + r) * N + bn + b_c);
                *(float4*)&Bs[r][b_c] = v;
            }
            __syncthreads();
#pragma unroll
            for (int kk = 0; kk < BK; kk++) {
                float4 a0 = *(const float4*)&As[kk][tr * 8];
                float4 a1 = *(const float4*)&As[kk][tr * 8 + 4];
                float4 b0 = *(const float4*)&Bs[kk][tc * 8];
                float4 b1 = *(const float4*)&Bs[kk][tc * 8 + 4];
                float a[8] = {a0.x, a0.y, a0.z, a0.w, a1.x, a1.y, a1.z, a1.w};
                float b[8] = {b0.x, b0.y, b0.z, b0.w, b1.x, b1.y, b1.z, b1.w};
#pragma unroll
                for (int i = 0; i < 8; i++)
#pragma unroll
                    for (int j = 0; j < 8; j++)
                        acc[i][j] = fmaf(a[i], b[j], acc[i][j]);
            }
            __syncthreads();
        }
    }
    const int row0 = bm + tr * 8, col0 = bn + tc * 8;
    float bias[8];
#pragma unroll
    for (int j = 0; j < 8; j++) {
        float v = bias1 ? bias1[col0 + j] : 0.0f;
        if (bias2) v += bias2[col0 + j];
        bias[j] = v;
    }
#pragma unroll
    for (int i = 0; i < 8; i++) {
        float4 o0, o1;
        o0.x = alpha * acc[i][0] + bias[0]; o0.y = alpha * acc[i][1] + bias[1];
        o0.z = alpha * acc[i][2] + bias[2]; o0.w = alpha * acc[i][3] + bias[3];
        o1.x = alpha * acc[i][4] + bias[4]; o1.y = alpha * acc[i][5] + bias[5];
        o1.z = alpha * acc[i][6] + bias[6]; o1.w = alpha * acc[i][7] + bias[7];
        *(float4*)(C + (long)(row0 + i) * ldc + col0)     = o0;
        *(float4*)(C + (long)(row0 + i) * ldc + col0 + 4) = o1;
    }
}

// bfused[n] = bp @ Wfc + bfc
__global__ void __launch_bounds__(256) r15_bfused_kernel(
    const float* __restrict__ bp, const float* __restrict__ Wfc,
    const float* __restrict__ bfc, float* __restrict__ out)
{
    const int n = blockIdx.x * 256 + threadIdx.x;
    float a0 = 0.f, a1 = 0.f, a2 = 0.f, a3 = 0.f;
    for (int k = 0; k < H_; k += 4) {
        a0 = fmaf(bp[k + 0], Wfc[(long)(k + 0) * H_ + n], a0);
        a1 = fmaf(bp[k + 1], Wfc[(long)(k + 1) * H_ + n], a1);
        a2 = fmaf(bp[k + 2], Wfc[(long)(k + 2) * H_ + n], a2);
        a3 = fmaf(bp[k + 3], Wfc[(long)(k + 3) * H_ + n], a3);
    }
    out[n] = ((a0 + a1) + (a2 + a3)) + bfc[n];
}

// WT[n][k] = W[k][n]
__global__ void __launch_bounds__(256) r15_transpose_kernel(
    const float* __restrict__ W, float* __restrict__ WT, int K, int N)
{
    __shared__ float tile[32][33];
    const int n0 = blockIdx.x * 32, k0 = blockIdx.y * 32;
    const int tx = threadIdx.x & 31, ty = threadIdx.x >> 5;
    for (int i = ty; i < 32; i += 8)
        tile[i][tx] = W[(long)(k0 + i) * N + n0 + tx];
    __syncthreads();
    for (int i = ty; i < 32; i += 8)
        WT[(long)(n0 + i) * K + k0 + tx] = tile[tx][i];
}

// ==================== elementwise step kernels ==============================
__inline__ __device__ float r15_warpsum(float v) {
#pragma unroll
    for (int o = 16; o > 0; o >>= 1) v += __shfl_xor_sync(0xffffffffu, v, o);
    return v;
}

__global__ void __launch_bounds__(256) r15_step1_kernel(
    const float* __restrict__ pre, long ldp, float* __restrict__ rec,
    float* __restrict__ ctx, float* __restrict__ s,
    const float* __restrict__ gamma, const float* __restrict__ beta)
{
    const int row = blockIdx.x;
    const float* p = pre + (long)row * ldp;
    float* r = rec + (long)row * H_;
    float vals[8];
    float sum = 0.f, sumsq = 0.f;
#pragma unroll
    for (int i = 0; i < 8; i++) {
        int h = threadIdx.x + i * 256;
        float u = tanhf(p[h]);
        float nr = 0.9f * r[h] + 0.1f * u;
        r[h] = nr; vals[i] = nr;
        sum += nr; sumsq += nr * nr;
    }
    float w1 = r15_warpsum(sum), w2 = r15_warpsum(sumsq);
    __shared__ float sh[16];
    int warp = threadIdx.x >> 5, lane = threadIdx.x & 31;
    if (lane == 0) { sh[warp] = w1; sh[8 + warp] = w2; }
    __syncthreads();
    if (threadIdx.x == 0) {
        float a = 0.f, b = 0.f;
#pragma unroll
        for (int i = 0; i < 8; i++) { a += sh[i]; b += sh[8 + i]; }
        sh[0] = a; sh[8] = b;
    }
    __syncthreads();
    const float mean = sh[0] * (1.0f / H_);
    const float var  = sh[8] * (1.0f / H_) - mean * mean;
    const float inv  = rsqrtf(var + 1e-5f);
#pragma unroll
    for (int i = 0; i < 8; i++) {
        int h = threadIdx.x + i * 256;
        float c = (vals[i] - mean) * inv * gamma[h] + beta[h];
        long o = (long)row * H_ + h;
        ctx[o] = c;
        s[o] = c + vals[i];
    }
}

__global__ void __launch_bounds__(256) r15_step2_kernel(
    const float* __restrict__ pre, const float* __restrict__ ctx,
    const float* __restrict__ rec, float* __restrict__ gated)
{
    long i = (long)blockIdx.x * blockDim.x + threadIdx.x;
    const float4 p = ((const float4*)pre)[i];
    const float4 c = ((const float4*)ctx)[i];
    const float4 r = ((const float4*)rec)[i];
    float4 o;
    float g;
    g = 1.0f / (1.0f + expf(-p.x)); o.x = g * c.x + (1.0f - g) * r.x;
    g = 1.0f / (1.0f + expf(-p.y)); o.y = g * c.y + (1.0f - g) * r.y;
    g = 1.0f / (1.0f + expf(-p.z)); o.z = g * c.z + (1.0f - g) * r.z;
    g = 1.0f / (1.0f + expf(-p.w)); o.w = g * c.w + (1.0f - g) * r.w;
    ((float4*)gated)[i] = o;
}

// step3 fast path: LIF + near-threshold MARKING (no inline refine)
__global__ void __launch_bounds__(256) r15_step3_kernel(
    const float* __restrict__ cur, const float* __restrict__ attr_in,
    float* __restrict__ attr_out, float* __restrict__ spk,
    int* __restrict__ cnt_t, int* __restrict__ list)
{
    long i = ((long)blockIdx.x * 256 + threadIdx.x) * 4;
    float4 c = *(const float4*)(cur + i);
    float4 a = *(const float4*)(attr_in + i);
    float4 sp = *(float4*)(spk + i);
    float cv[4] = { c.x, c.y, c.z, c.w };
    float av[4] = { a.x, a.y, a.z, a.w };
    float sv[4] = { sp.x, sp.y, sp.z, sp.w };
#pragma unroll
    for (int k = 0; k < 4; k++) {
        float v = av[k] + (cv[k] - av[k]) * 0.5f;
        float s = (v > 1.0f) ? 1.0f : 0.0f;
        if (fabsf(v - 1.0f) < 1e-4f) {
            int idx = atomicAdd(cnt_t, 1);
            if (idx < LIST_MAX)
                list[idx] = (int)(((i + k) << 1) | (int)s);
        }
        av[k] = v - s; sv[k] += s;
    }
    *(float4*)(attr_out + i) = make_float4(av[0], av[1], av[2], av[3]);
    *(float4*)(spk + i)      = make_float4(sv[0], sv[1], sv[2], sv[3]);
}

// cooperative fp64 refine: one block per listed element
__global__ void __launch_bounds__(256) r15_refine_kernel(
    const int* __restrict__ cnt_t, const int* __restrict__ list,
    const float* __restrict__ attr_in, float* __restrict__ attr_out,
    float* __restrict__ spk, const float* __restrict__ gf,
    const float* __restrict__ WencT, const float* __restrict__ benc,
    const float* __restrict__ WrecT, const float* __restrict__ brec)
{
    __shared__ double red[8];
    const int n = min(*cnt_t, LIST_MAX);
    const int tid = threadIdx.x;
    for (int item = blockIdx.x; item < n; item += gridDim.x) {
        const int packed = list[item];
        const long elem = (long)(packed >> 1);
        const float s_old = (float)(packed & 1);
        const long row = elem / H_;
        const int  h   = (int)(elem % H_);
        const float* grow = gf + row * H_;
        const float* arow = attr_in + row * H_;
        const float* we = WencT + (long)h * H_;
        const float* wr = WrecT + (long)h * H_;
        double d = 0.0;
        for (int kk = tid; kk < H_; kk += 256)
            d += (double)grow[kk] * (double)we[kk]
               + (double)arow[kk] * (double)wr[kk];
        // block reduce (deterministic tree)
        double w = d;
#pragma unroll
        for (int o = 16; o > 0; o >>= 1)
            w += __shfl_xor_sync(0xffffffffu, w, o);
        if ((tid & 31) == 0) red[tid >> 5] = w;
        __syncthreads();
        if (tid == 0) {
            double acc = (double)benc[h] + (double)brec[h];
#pragma unroll
            for (int q = 0; q < 8; q++) acc += red[q];
            float av_old = attr_in[elem];
            float v = av_old + ((float)acc - av_old) * 0.5f;
            float s_new = (v > 1.0f) ? 1.0f : 0.0f;
            attr_out[elem] = v - s_new;
            spk[elem] += (s_new - s_old);
        }
        __syncthreads();
    }
}

__global__ void __launch_bounds__(256) r15_init_kernel(
    float* __restrict__ rec, float* __restrict__ attr, float* __restrict__ spk,
    int* __restrict__ cnt)
{
    long i = (long)blockIdx.x * blockDim.x + threadIdx.x;
    if (i < T_) cnt[i] = 0;
    float4 z = make_float4(0.f, 0.f, 0.f, 0.f);
    ((float4*)rec)[i] = z; ((float4*)attr)[i] = z; ((float4*)spk)[i] = z;
}

__global__ void __launch_bounds__(256) r15_tail_kernel(
    const float* __restrict__ rec, const float* __restrict__ attr, float* __restrict__ out)
{
    long i = (long)blockIdx.x * blockDim.x + threadIdx.x;
    ((float4*)out)[i] = ((const float4*)rec)[i];
    ((float4*)(out + (long)B_ * H_))[i] = ((const float4*)attr)[i];
}

// ==================== launch =================================================
#define GETSYM(var, sym) cudaGetSymbolAddress((void**)&var, sym)

extern "C" void kernel_launch(void* const* d_in, const int* in_sizes, int n_in,
                              void* d_out, int out_size)
{
    const float* x    = (const float*)d_in[0];
    const float* Wp   = (const float*)d_in[1];
    const float* bp   = (const float*)d_in[2];
    const float* Wfc  = (const float*)d_in[3];
    const float* bfc  = (const float*)d_in[4];
    const float* gamma= (const float*)d_in[5];
    const float* beta = (const float*)d_in[6];
    const float* Wg   = (const float*)d_in[7];
    const float* bg   = (const float*)d_in[8];
    const float* Wenc = (const float*)d_in[9];
    const float* benc = (const float*)d_in[10];
    const float* Wrec = (const float*)d_in[11];
    const float* brec = (const float*)d_in[12];
    const float* Wro  = (const float*)d_in[13];
    const float* bro  = (const float*)d_in[14];
    float* out = (float*)d_out;

    float *Wfused, *bfused, *WencT, *WrecT, *preall, *pre, *sf, *gf;
    float *ctx, *rec, *attrA, *attrB, *spk;
    int *cnt, *list;
    GETSYM(Wfused, r15_Wfused); GETSYM(bfused, r15_bfused);
    GETSYM(WencT, r15_WencT);   GETSYM(WrecT, r15_WrecT);
    GETSYM(preall, r15_preall); GETSYM(pre, r15_pre);
    GETSYM(sf, r15_sf);         GETSYM(gf, r15_gf);
    GETSYM(ctx, r15_ctx);       GETSYM(rec, r15_rec);
    GETSYM(attrA, r15_attrA);   GETSYM(attrB, r15_attrB);
    GETSYM(spk, r15_spk);
    GETSYM(cnt, r15_cnt);       GETSYM(list, r15_list);

    const int EW = (B_ * H_ / 4) / 256;  // 2048 blocks

    r15_init_kernel<<<EW, 256>>>(rec, attrA, spk, cnt);

    // one-time prep
    r15_sgemm<<<dim3(H_ / 128, D_ / 128), 256>>>(
        Wp, H_, Wfc, nullptr, 0, nullptr,
        nullptr, nullptr, Wfused, H_, D_, H_, H_, 1.0f);
    r15_bfused_kernel<<<H_ / 256, 256>>>(bp, Wfc, bfc, bfused);
    r15_transpose_kernel<<<dim3(H_ / 32, H_ / 32), 256>>>(Wenc, WencT, H_, H_);
    r15_transpose_kernel<<<dim3(H_ / 32, H_ / 32), 256>>>(Wrec, WrecT, H_, H_);

    // batched pre-activation: preall = x @ Wfused + bfused  (M=B*T, K=D)
    r15_sgemm<<<dim3(H_ / 128, (B_ * T_) / 128), 256>>>(
        x, D_, Wfused, nullptr, 0, nullptr,
        bfused, nullptr, preall, H_, B_ * T_, H_, D_, 1.0f);

    const dim3 gstep(H_ / 128, B_ / 128);  // (16, 8)
    for (int t = 0; t < T_; t++) {
        float* attr_in  = (t & 1) ? attrB : attrA;
        float* attr_out = (t & 1) ? attrA : attrB;
        r15_step1_kernel<<<B_, 256>>>(preall + (long)t * H_, (long)T_ * H_,
                                      rec, ctx, sf, gamma, beta);
        r15_sgemm<<<gstep, 256>>>(sf, H_, Wg, nullptr, 0, nullptr,
                                  bg, nullptr, pre, H_, B_, H_, H_, 1.0f);
        r15_step2_kernel<<<EW, 256>>>(pre, ctx, rec, gf);
        r15_sgemm<<<gstep, 256>>>(gf, H_, Wenc, attr_in, H_, Wrec,
                                  benc, brec, pre, H_, B_, H_, H_, 1.0f);
        r15_step3_kernel<<<EW, 256>>>(pre, attr_in, attr_out, spk,
                                      cnt + t, list);
        r15_refine_kernel<<<2048, 256>>>(cnt + t, list, attr_in, attr_out, spk,
                                         gf, WencT, benc, WrecT, brec);
    }

    // readout
    r15_sgemm<<<dim3(O_ / 128, B_ / 128), 256>>>(
        spk, H_, Wro, nullptr, 0, nullptr,
        bro, nullptr, out, O_, B_, O_, H_, 1.0f / 16.0f);
    r15_tail_kernel<<<EW, 256>>>(rec, attrA, out + (long)B_ * O_);
}

// round 16
// speedup vs baseline: 2.3752x; 1.2058x over previous
#include <cuda_runtime.h>
#include <math.h>
#include <stdint.h>

#define B_ 1024
#define T_ 16
#define D_ 1024
#define H_ 2048
#define O_ 1024
#define LIST_MAX (1 << 20)

// ==================== device globals ========================================
__device__ float r16_Wfused[D_ * H_];
__device__ float r16_bfused[H_];
__device__ float r16_WencT[H_ * H_], r16_WrecT[H_ * H_];
__device__ float r16_preall[B_ * T_ * H_];   // x@Wfused+bfused, then reused pattern below
__device__ float r16_pre2all[B_ * T_ * H_];  // sall@Wg+bg
__device__ float r16_sall[B_ * T_ * H_];
__device__ float r16_recall[B_ * T_ * H_];
__device__ float r16_ctxall[B_ * T_ * H_];
__device__ float r16_gatedall[B_ * T_ * H_];
__device__ float r16_encall[B_ * T_ * H_];   // gated@Wenc + benc + brec
__device__ float r16_cur[B_ * H_];
__device__ float r16_attrA[B_ * H_], r16_attrB[B_ * H_];
__device__ float r16_spk[B_ * H_];
__device__ int   r16_cnt[T_];
__device__ int   r16_list[LIST_MAX];

// ==================== fp32 SGEMM (proven engine + optional Cin add) ========
__global__ void __launch_bounds__(256) r16_sgemm(
    const float* __restrict__ A1, int lda1, const float* __restrict__ B1,
    const float* __restrict__ bias1, const float* __restrict__ bias2,
    const float* __restrict__ Cin, long ldcin,
    float* __restrict__ C, int ldc, int M, int N, int K, float alpha)
{
    const int BM = 128, BN = 128, BK = 16;
    __shared__ float As[BK][BM];
    __shared__ float Bs[BK][BN];
    const int bm = blockIdx.y * BM, bn = blockIdx.x * BN;
    const int tid = threadIdx.x, tr = tid / 16, tc = tid % 16;
    const int a_r = tid / 4, a_c = (tid % 4) * 4;
    const int b_r = tid / 32, b_c = (tid % 32) * 4;

    float acc[8][8];
#pragma unroll
    for (int i = 0; i < 8; i++)
#pragma unroll
        for (int j = 0; j < 8; j++) acc[i][j] = 0.0f;

    for (int k0 = 0; k0 < K; k0 += BK) {
#pragma unroll
        for (int i = 0; i < 2; i++) {
            int r = a_r + i * 64;
            float4 v = *(const float4*)(A1 + (long)(bm + r) * lda1 + k0 + a_c);
            As[a_c + 0][r] = v.x; As[a_c + 1][r] = v.y;
            As[a_c + 2][r] = v.z; As[a_c + 3][r] = v.w;
        }
#pragma unroll
        for (int i = 0; i < 2; i++) {
            int r = b_r + i * 8;
            float4 v = *(const float4*)(B1 + (long)(k0 + r) * N + bn + b_c);
            *(float4*)&Bs[r][b_c] = v;
        }
        __syncthreads();
#pragma unroll
        for (int kk = 0; kk < BK; kk++) {
            float4 a0 = *(const float4*)&As[kk][tr * 8];
            float4 a1 = *(const float4*)&As[kk][tr * 8 + 4];
            float4 b0 = *(const float4*)&Bs[kk][tc * 8];
            float4 b1 = *(const float4*)&Bs[kk][tc * 8 + 4];
            float a[8] = {a0.x, a0.y, a0.z, a0.w, a1.x, a1.y, a1.z, a1.w};
            float b[8] = {b0.x, b0.y, b0.z, b0.w, b1.x, b1.y, b1.z, b1.w};
#pragma unroll
            for (int i = 0; i < 8; i++)
#pragma unroll
                for (int j = 0; j < 8; j++)
                    acc[i][j] = fmaf(a[i], b[j], acc[i][j]);
        }
        __syncthreads();
    }
    const int row0 = bm + tr * 8, col0 = bn + tc * 8;
    float bias[8];
#pragma unroll
    for (int j = 0; j < 8; j++) {
        float v = bias1 ? bias1[col0 + j] : 0.0f;
        if (bias2) v += bias2[col0 + j];
        bias[j] = v;
    }
#pragma unroll
    for (int i = 0; i < 8; i++) {
        float c[8];
#pragma unroll
        for (int j = 0; j < 8; j++) c[j] = alpha * acc[i][j] + bias[j];
        if (Cin) {
            float4 ci0 = *(const float4*)(Cin + (long)(row0 + i) * ldcin + col0);
            float4 ci1 = *(const float4*)(Cin + (long)(row0 + i) * ldcin + col0 + 4);
            c[0] += ci0.x; c[1] += ci0.y; c[2] += ci0.z; c[3] += ci0.w;
            c[4] += ci1.x; c[5] += ci1.y; c[6] += ci1.z; c[7] += ci1.w;
        }
        *(float4*)(C + (long)(row0 + i) * ldc + col0)     = make_float4(c[0], c[1], c[2], c[3]);
        *(float4*)(C + (long)(row0 + i) * ldc + col0 + 4) = make_float4(c[4], c[5], c[6], c[7]);
    }
}

// bfused[n] = bp @ Wfc + bfc
__global__ void __launch_bounds__(256) r16_bfused_kernel(
    const float* __restrict__ bp, const float* __restrict__ Wfc,
    const float* __restrict__ bfc, float* __restrict__ out)
{
    const int n = blockIdx.x * 256 + threadIdx.x;
    float a0 = 0.f, a1 = 0.f, a2 = 0.f, a3 = 0.f;
    for (int k = 0; k < H_; k += 4) {
        a0 = fmaf(bp[k + 0], Wfc[(long)(k + 0) * H_ + n], a0);
        a1 = fmaf(bp[k + 1], Wfc[(long)(k + 1) * H_ + n], a1);
        a2 = fmaf(bp[k + 2], Wfc[(long)(k + 2) * H_ + n], a2);
        a3 = fmaf(bp[k + 3], Wfc[(long)(k + 3) * H_ + n], a3);
    }
    out[n] = ((a0 + a1) + (a2 + a3)) + bfc[n];
}

// WT[n][k] = W[k][n]
__global__ void __launch_bounds__(256) r16_transpose_kernel(
    const float* __restrict__ W, float* __restrict__ WT, int K, int N)
{
    __shared__ float tile[32][33];
    const int n0 = blockIdx.x * 32, k0 = blockIdx.y * 32;
    const int tx = threadIdx.x & 31, ty = threadIdx.x >> 5;
    for (int i = ty; i < 32; i += 8)
        tile[i][tx] = W[(long)(k0 + i) * N + n0 + tx];
    __syncthreads();
    for (int i = ty; i < 32; i += 8)
        WT[(long)(n0 + i) * K + k0 + tx] = tile[tx][i];
}

// ==================== rec-chain: all 16 steps of rec/ctx/s, elementwise ====
__inline__ __device__ float r16_warpsum(float v) {
#pragma unroll
    for (int o = 16; o > 0; o >>= 1) v += __shfl_xor_sync(0xffffffffu, v, o);
    return v;
}

__global__ void __launch_bounds__(256) r16_chain_kernel(
    const float* __restrict__ preall, float* __restrict__ recall,
    float* __restrict__ ctxall, float* __restrict__ sall,
    const float* __restrict__ gamma, const float* __restrict__ beta)
{
    const int b = blockIdx.x;
    __shared__ float sh[16];
    const int warp = threadIdx.x >> 5, lane = threadIdx.x & 31;

    float rec[8];
#pragma unroll
    for (int i = 0; i < 8; i++) rec[i] = 0.0f;

    for (int t = 0; t < T_; t++) {
        const long base = ((long)b * T_ + t) * H_;
        float sum = 0.f, sumsq = 0.f;
#pragma unroll
        for (int i = 0; i < 8; i++) {
            int h = threadIdx.x + i * 256;
            float u = tanhf(preall[base + h]);
            float nr = 0.9f * rec[i] + 0.1f * u;
            rec[i] = nr;
            sum += nr; sumsq += nr * nr;
        }
        float w1 = r16_warpsum(sum), w2 = r16_warpsum(sumsq);
        if (lane == 0) { sh[warp] = w1; sh[8 + warp] = w2; }
        __syncthreads();
        if (threadIdx.x == 0) {
            float a = 0.f, c = 0.f;
#pragma unroll
            for (int i = 0; i < 8; i++) { a += sh[i]; c += sh[8 + i]; }
            sh[0] = a; sh[8] = c;
        }
        __syncthreads();
        const float mean = sh[0] * (1.0f / H_);
        const float var  = sh[8] * (1.0f / H_) - mean * mean;
        const float inv  = rsqrtf(var + 1e-5f);
#pragma unroll
        for (int i = 0; i < 8; i++) {
            int h = threadIdx.x + i * 256;
            float c = (rec[i] - mean) * inv * gamma[h] + beta[h];
            recall[base + h] = rec[i];
            ctxall[base + h] = c;
            sall[base + h]   = c + rec[i];
        }
        __syncthreads();
    }
}

// gatedall = sigmoid(pre2all) * ctxall + (1-sigmoid) * recall   (all t at once)
__global__ void __launch_bounds__(256) r16_gated_kernel(
    const float* __restrict__ pre2, const float* __restrict__ ctx,
    const float* __restrict__ rec, float* __restrict__ gated)
{
    long i = (long)blockIdx.x * blockDim.x + threadIdx.x;
    const float4 p = ((const float4*)pre2)[i];
    const float4 c = ((const float4*)ctx)[i];
    const float4 r = ((const float4*)rec)[i];
    float4 o;
    float g;
    g = 1.0f / (1.0f + expf(-p.x)); o.x = g * c.x + (1.0f - g) * r.x;
    g = 1.0f / (1.0f + expf(-p.y)); o.y = g * c.y + (1.0f - g) * r.y;
    g = 1.0f / (1.0f + expf(-p.z)); o.z = g * c.z + (1.0f - g) * r.z;
    g = 1.0f / (1.0f + expf(-p.w)); o.w = g * c.w + (1.0f - g) * r.w;
    ((float4*)gated)[i] = o;
}

// step3 fast path: LIF + near-threshold marking
__global__ void __launch_bounds__(256) r16_step3_kernel(
    const float* __restrict__ cur, const float* __restrict__ attr_in,
    float* __restrict__ attr_out, float* __restrict__ spk,
    int* __restrict__ cnt_t, int* __restrict__ list)
{
    long i = ((long)blockIdx.x * 256 + threadIdx.x) * 4;
    float4 c = *(const float4*)(cur + i);
    float4 a = *(const float4*)(attr_in + i);
    float4 sp = *(float4*)(spk + i);
    float cv[4] = { c.x, c.y, c.z, c.w };
    float av[4] = { a.x, a.y, a.z, a.w };
    float sv[4] = { sp.x, sp.y, sp.z, sp.w };
#pragma unroll
    for (int k = 0; k < 4; k++) {
        float v = av[k] + (cv[k] - av[k]) * 0.5f;
        float s = (v > 1.0f) ? 1.0f : 0.0f;
        if (fabsf(v - 1.0f) < 1e-4f) {
            int idx = atomicAdd(cnt_t, 1);
            if (idx < LIST_MAX)
                list[idx] = (int)(((i + k) << 1) | (int)s);
        }
        av[k] = v - s; sv[k] += s;
    }
    *(float4*)(attr_out + i) = make_float4(av[0], av[1], av[2], av[3]);
    *(float4*)(spk + i)      = make_float4(sv[0], sv[1], sv[2], sv[3]);
}

// cooperative fp64 refine (gated rows live in gatedall with stride T*H)
__global__ void __launch_bounds__(256) r16_refine_kernel(
    const int* __restrict__ cnt_t, const int* __restrict__ list,
    const float* __restrict__ attr_in, float* __restrict__ attr_out,
    float* __restrict__ spk, const float* __restrict__ gbase, long gstride,
    const float* __restrict__ WencT, const float* __restrict__ benc,
    const float* __restrict__ WrecT, const float* __restrict__ brec)
{
    __shared__ double red[8];
    const int n = min(*cnt_t, LIST_MAX);
    const int tid = threadIdx.x;
    for (int item = blockIdx.x; item < n; item += gridDim.x) {
        const int packed = list[item];
        const long elem = (long)(packed >> 1);
        const float s_old = (float)(packed & 1);
        const long row = elem / H_;
        const int  h   = (int)(elem % H_);
        const float* grow = gbase + row * gstride;
        const float* arow = attr_in + row * H_;
        const float* we = WencT + (long)h * H_;
        const float* wr = WrecT + (long)h * H_;
        double d = 0.0;
        for (int kk = tid; kk < H_; kk += 256)
            d += (double)grow[kk] * (double)we[kk]
               + (double)arow[kk] * (double)wr[kk];
        double w = d;
#pragma unroll
        for (int o = 16; o > 0; o >>= 1)
            w += __shfl_xor_sync(0xffffffffu, w, o);
        if ((tid & 31) == 0) red[tid >> 5] = w;
        __syncthreads();
        if (tid == 0) {
            double acc = (double)benc[h] + (double)brec[h];
#pragma unroll
            for (int q = 0; q < 8; q++) acc += red[q];
            float av_old = attr_in[elem];
            float v = av_old + ((float)acc - av_old) * 0.5f;
            float s_new = (v > 1.0f) ? 1.0f : 0.0f;
            attr_out[elem] = v - s_new;
            spk[elem] += (s_new - s_old);
        }
        __syncthreads();
    }
}

__global__ void __launch_bounds__(256) r16_init_kernel(
    float* __restrict__ attr, float* __restrict__ spk, int* __restrict__ cnt)
{
    long i = (long)blockIdx.x * blockDim.x + threadIdx.x;
    if (i < T_) cnt[i] = 0;
    float4 z = make_float4(0.f, 0.f, 0.f, 0.f);
    ((float4*)attr)[i] = z; ((float4*)spk)[i] = z;
}

// out tail: rec comes from recall at t = T-1 (row stride T*H)
__global__ void __launch_bounds__(256) r16_tail_kernel(
    const float* __restrict__ recall, const float* __restrict__ attr,
    float* __restrict__ out)
{
    long i = (long)blockIdx.x * blockDim.x + threadIdx.x;   // over B*H/4
    long e4 = i * 4;
    long b = e4 / H_;
    long h = e4 % H_;
    float4 rv = *(const float4*)(recall + ((long)b * T_ + (T_ - 1)) * H_ + h);
    ((float4*)out)[i] = rv;
    ((float4*)(out + (long)B_ * H_))[i] = ((const float4*)attr)[i];
}

// ==================== launch =================================================
#define GETSYM(var, sym) cudaGetSymbolAddress((void**)&var, sym)

extern "C" void kernel_launch(void* const* d_in, const int* in_sizes, int n_in,
                              void* d_out, int out_size)
{
    const float* x    = (const float*)d_in[0];
    const float* Wp   = (const float*)d_in[1];
    const float* bp   = (const float*)d_in[2];
    const float* Wfc  = (const float*)d_in[3];
    const float* bfc  = (const float*)d_in[4];
    const float* gamma= (const float*)d_in[5];
    const float* beta = (const float*)d_in[6];
    const float* Wg   = (const float*)d_in[7];
    const float* bg   = (const float*)d_in[8];
    const float* Wenc = (const float*)d_in[9];
    const float* benc = (const float*)d_in[10];
    const float* Wrec = (const float*)d_in[11];
    const float* brec = (const float*)d_in[12];
    const float* Wro  = (const float*)d_in[13];
    const float* bro  = (const float*)d_in[14];
    float* out = (float*)d_out;

    float *Wfused, *bfused, *WencT, *WrecT;
    float *preall, *pre2all, *sall, *recall, *ctxall, *gatedall, *encall;
    float *cur, *attrA, *attrB, *spk;
    int *cnt, *list;
    GETSYM(Wfused, r16_Wfused);   GETSYM(bfused, r16_bfused);
    GETSYM(WencT, r16_WencT);     GETSYM(WrecT, r16_WrecT);
    GETSYM(preall, r16_preall);   GETSYM(pre2all, r16_pre2all);
    GETSYM(sall, r16_sall);       GETSYM(recall, r16_recall);
    GETSYM(ctxall, r16_ctxall);   GETSYM(gatedall, r16_gatedall);
    GETSYM(encall, r16_encall);
    GETSYM(cur, r16_cur);
    GETSYM(attrA, r16_attrA);     GETSYM(attrB, r16_attrB);
    GETSYM(spk, r16_spk);
    GETSYM(cnt, r16_cnt);         GETSYM(list, r16_list);

    const int EW = (B_ * H_ / 4) / 256;         // 2048 blocks
    const dim3 gbig(H_ / 128, (B_ * T_) / 128); // (16, 128)
    const dim3 gstep(H_ / 128, B_ / 128);       // (16, 8)

    r16_init_kernel<<<EW, 256>>>(attrA, spk, cnt);

    // prep: fold, bfused, transposes
    r16_sgemm<<<dim3(H_ / 128, D_ / 128), 256>>>(
        Wp, H_, Wfc, nullptr, nullptr, nullptr, 0,
        Wfused, H_, D_, H_, H_, 1.0f);
    r16_bfused_kernel<<<H_ / 256, 256>>>(bp, Wfc, bfc, bfused);
    r16_transpose_kernel<<<dim3(H_ / 32, H_ / 32), 256>>>(Wenc, WencT, H_, H_);
    r16_transpose_kernel<<<dim3(H_ / 32, H_ / 32), 256>>>(Wrec, WrecT, H_, H_);

    // preall = x @ Wfused + bfused    (M=B*T, K=D)
    r16_sgemm<<<gbig, 256>>>(x, D_, Wfused, bfused, nullptr, nullptr, 0,
                             preall, H_, B_ * T_, H_, D_, 1.0f);

    // rec chain: all rec/ctx/s for 16 steps (elementwise + per-row LN)
    r16_chain_kernel<<<B_, 256>>>(preall, recall, ctxall, sall, gamma, beta);

    // batched GEMM2: pre2all = sall @ Wg + bg   (M=B*T, K=H)
    r16_sgemm<<<gbig, 256>>>(sall, H_, Wg, bg, nullptr, nullptr, 0,
                             pre2all, H_, B_ * T_, H_, H_, 1.0f);

    // gatedall for all steps
    r16_gated_kernel<<<(B_ * T_ * H_ / 4) / 256, 256>>>(pre2all, ctxall, recall, gatedall);

    // batched enc half of GEMM3: encall = gatedall @ Wenc + benc + brec
    r16_sgemm<<<gbig, 256>>>(gatedall, H_, Wenc, benc, brec, nullptr, 0,
                             encall, H_, B_ * T_, H_, H_, 1.0f);

    // sequential attr recurrence: only attr@Wrec per step
    for (int t = 0; t < T_; t++) {
        float* attr_in  = (t & 1) ? attrB : attrA;
        float* attr_out = (t & 1) ? attrA : attrB;
        // cur = attr_in @ Wrec + encall(t)
        r16_sgemm<<<gstep, 256>>>(attr_in, H_, Wrec, nullptr, nullptr,
                                  encall + (long)t * H_, (long)T_ * H_,
                                  cur, H_, B_, H_, H_, 1.0f);
        r16_step3_kernel<<<EW, 256>>>(cur, attr_in, attr_out, spk, cnt + t, list);
        r16_refine_kernel<<<232, 256>>>(cnt + t, list, attr_in, attr_out, spk,
                                        gatedall + (long)t * H_, (long)T_ * H_,
                                        WencT, benc, WrecT, brec);
    }

    // readout: out = (spk/16) @ Wro + bro
    r16_sgemm<<<dim3(O_ / 128, B_ / 128), 256>>>(
        spk, H_, Wro, bro, nullptr, nullptr, 0,
        out, O_, B_, O_, H_, 1.0f / 16.0f);
    r16_tail_kernel<<<EW, 256>>>(recall, attrA, out + (long)B_ * O_);
}